// round 16
// baseline (speedup 1.0000x reference)
#include <cuda_runtime.h>
#include <cuda_fp16.h>
#include <cstdint>
#include <cstddef>

// out[M,N] = x[M,K] @ (w[K,N] + 2 * lora_a[K,16] @ lora_b[16,N])
#define M_DIM 8192
#define N_DIM 8192
#define K_DIM 2048
#define SCALE 2.0f

// Scratch (device globals — allocation-free per harness rules).
__device__ __align__(16) __half g_xh[(size_t)M_DIM * K_DIM];  // x -> fp16 [M,K]
__device__ __align__(16) __half g_wh[(size_t)N_DIM * K_DIM];  // W'^T fp16 [N,K]

// ---------------------------------------------------------------------------
// Kernel 1: x -> fp16, straight layout. One thread: 8 floats -> 8 halves.
// ---------------------------------------------------------------------------
__global__ __launch_bounds__(256) void prep_x(const float4* __restrict__ x,
                                              uint4* __restrict__ xh) {
    const size_t i = (size_t)blockIdx.x * 256 + threadIdx.x;
    const float4 v0 = x[i * 2 + 0];
    const float4 v1 = x[i * 2 + 1];
    __half2 h[4];
    h[0] = __floats2half2_rn(v0.x, v0.y);
    h[1] = __floats2half2_rn(v0.z, v0.w);
    h[2] = __floats2half2_rn(v1.x, v1.y);
    h[3] = __floats2half2_rn(v1.z, v1.w);
    xh[i] = *reinterpret_cast<const uint4*>(h);
}

// ---------------------------------------------------------------------------
// Kernel 2: g_wh[n][k] = fp16(w[k][n] + 2*(A@B)[k][n]).
// Tile 64k x 32n per block; uint4-packed coalesced stores.
// ---------------------------------------------------------------------------
__global__ __launch_bounds__(256) void fuse_w_t(const float* __restrict__ w,
                                                const float* __restrict__ la,
                                                const float* __restrict__ lb) {
    __shared__ float t[64][33];
    __shared__ float bs[16][32];
    const int n0 = blockIdx.x * 32, k0 = blockIdx.y * 64;
    const int tid = threadIdx.x;
    const int tx = tid & 31, ty = tid >> 5;
    {
        int i0 = tid;
        bs[i0 >> 5][i0 & 31] = lb[(size_t)(i0 >> 5) * N_DIM + n0 + (i0 & 31)];
        int i1 = tid + 256;
        bs[i1 >> 5][i1 & 31] = lb[(size_t)(i1 >> 5) * N_DIM + n0 + (i1 & 31)];
    }
    __syncthreads();
#pragma unroll
    for (int i = 0; i < 8; i++) {
        const int kl = ty + 8 * i;           // 0..63
        const int k = k0 + kl;
        const float* ar = la + (size_t)k * 16;
        float acc = 0.f;
#pragma unroll
        for (int r = 0; r < 16; r++) acc += ar[r] * bs[r][tx];
        t[kl][tx] = w[(size_t)k * N_DIM + n0 + tx] + SCALE * acc;
    }
    __syncthreads();
    const int nl = tid >> 3;                 // 0..31
    const int kc = (tid & 7) * 8;            // 0..56
    __half2 h[4];
#pragma unroll
    for (int j = 0; j < 4; j++)
        h[j] = __halves2half2(__float2half_rn(t[kc + 2 * j][nl]),
                              __float2half_rn(t[kc + 2 * j + 1][nl]));
    *reinterpret_cast<uint4*>(&g_wh[(size_t)(n0 + nl) * K_DIM + k0 + kc]) =
        *reinterpret_cast<const uint4*>(h);
}

// ---------------------------------------------------------------------------
// Kernel 3: PERSISTENT fp16 mma.sync GEMM (f32 accum). 304 CTAs (2/SM),
// 128 threads, 4 warps of 64x64. KTILE=32, 4 stages, wait_group 2.
// Schedule: 13 full 128x128 tiles per CTA (= 3952), plus the 144 leftover
// tiles split into 288 half-tiles of 128x64 (full K) taken by CTAs 0..287.
// Halves cost ~0.6 of a full step -> tail shrinks from +64 to ~+38 step-eq.
// ---------------------------------------------------------------------------
constexpr int KTILE = 32;                   // halves per k-tile
constexpr int STRIDE = 40;                  // 80 B rows; LDSM banks 20r distinct
constexpr int T_ST = 128 * STRIDE;          // 5120 halves (10 KB)
constexpr int STAGE = 2 * T_ST;             // A + B per stage (20 KB)
constexpr int SMEM_BYTES = 4 * STAGE * 2;   // 81920 B (x2 CTAs = 160 KB)
constexpr int KTILES = K_DIM / KTILE;       // 64 steps per tile
constexpr int NT = (M_DIM / 128) * (N_DIM / 128);  // 4096 tiles
constexpr int GRID = 304;                   // 152 SMs x 2 CTAs
constexpr int FULLS = 13;                   // full tiles per CTA
constexpr int NT_FULL = GRID * FULLS;       // 3952
constexpr int HALF_CTAS = 2 * (NT - NT_FULL);  // 288 half-tiles
constexpr int FULL_STEPS = FULLS * KTILES;  // 832

__device__ __forceinline__ void ldsm4(uint32_t& r0, uint32_t& r1, uint32_t& r2,
                                      uint32_t& r3, uint32_t addr) {
    asm volatile("ldmatrix.sync.aligned.m8n8.x4.shared.b16 {%0,%1,%2,%3}, [%4];"
                 : "=r"(r0), "=r"(r1), "=r"(r2), "=r"(r3) : "r"(addr));
}
__device__ __forceinline__ void mma16(float c[4], const uint32_t a[4], const uint32_t b[2]) {
    asm volatile(
        "mma.sync.aligned.m16n8k16.row.col.f32.f16.f16.f32 "
        "{%0,%1,%2,%3}, {%4,%5,%6,%7}, {%8,%9}, {%0,%1,%2,%3};\n"
        : "+f"(c[0]), "+f"(c[1]), "+f"(c[2]), "+f"(c[3])
        : "r"(a[0]), "r"(a[1]), "r"(a[2]), "r"(a[3]), "r"(b[0]), "r"(b[1]));
}

__global__ __launch_bounds__(128, 2) void gemm_f16(const __half* __restrict__ A,
                                                   const __half* __restrict__ B,
                                                   float* __restrict__ C) {
    extern __shared__ __half smem[];
    const int tid = threadIdx.x;
    const int lane = tid & 31;
    const int warp = tid >> 5;   // 0..3
    const int wm = warp >> 1;    // 2 warps along M (64 rows)
    const int wn = warp & 1;     // 2 warps along N
    const int grp = lane >> 2;   // 0..7
    const int tig = lane & 3;    // 0..3
    const int cta = blockIdx.x;

    const uint32_t smem_u = (uint32_t)__cvta_generic_to_shared(smem);

    const bool has_half = (cta < HALF_CTAS);
    const int total_g = FULL_STEPS + (has_half ? KTILES : 0);

    // half-tile coords (valid if has_half)
    const int htl = NT_FULL + (cta >> 1);
    const int hbM = (htl >> 6) * 128;
    const int hbN = (htl & 63) * 128 + (cta & 1) * 64;

    float acc[4][8][4];
#pragma unroll
    for (int i = 0; i < 4; i++)
#pragma unroll
        for (int j = 0; j < 8; j++)
#pragma unroll
            for (int l = 0; l < 4; l++) acc[i][j][l] = 0.f;

    // Pipeline step l: full tiles for l < FULL_STEPS, then the half-tile.
    auto load_stage = [&](int l) {
        int bM, bN, k0, brows;
        if (l < FULL_STEPS) {
            const int tl = cta + (l >> 6) * GRID;
            bM = (tl >> 6) * 128;
            bN = (tl & 63) * 128;
            k0 = (l & 63) * KTILE;
            brows = 4;                        // 128 B-rows (4 iters)
        } else {
            bM = hbM;
            bN = hbN;
            k0 = (l - FULL_STEPS) * KTILE;
            brows = 2;                        // 64 B-rows (2 iters)
        }
        const uint32_t baseA = smem_u + (uint32_t)((l & 3) * STAGE) * 2u;
        const uint32_t baseB = baseA + (uint32_t)T_ST * 2u;
#pragma unroll
        for (int i = 0; i < 4; i++) {
            const int idx = tid + i * 128;
            const int row = idx >> 2, ch = idx & 3;
            const __half* g = A + (size_t)(bM + row) * K_DIM + k0 + ch * 8;
            const uint32_t d = baseA + (uint32_t)(row * STRIDE + ch * 8) * 2u;
            asm volatile("cp.async.cg.shared.global [%0], [%1], 16;\n" ::"r"(d), "l"(g));
        }
        for (int i = 0; i < brows; i++) {
            const int idx = tid + i * 128;
            const int row = idx >> 2, ch = idx & 3;
            const __half* g = B + (size_t)(bN + row) * K_DIM + k0 + ch * 8;
            const uint32_t d = baseB + (uint32_t)(row * STRIDE + ch * 8) * 2u;
            asm volatile("cp.async.cg.shared.global [%0], [%1], 16;\n" ::"r"(d), "l"(g));
        }
    };

    // Prologue: steps 0,1,2 -> stages 0,1,2 (all full-tile steps)
#pragma unroll
    for (int p = 0; p < 3; p++) {
        load_stage(p);
        asm volatile("cp.async.commit_group;\n" ::: "memory");
    }

    // ldmatrix per-thread addresses (mapping validated round 8):
    const int aRow = wm * 64 + (lane & 7) + 8 * ((lane >> 3) & 1);
    const int aKc = (lane >> 4) & 1;
    const int bRow = wn * 64 + (lane & 7) + 8 * ((lane >> 4) & 1);   // full
    const int bRowH = wn * 32 + (lane & 7) + 8 * ((lane >> 4) & 1);  // half
    const int bKc = (lane >> 3) & 1;

    for (int g = 0; g < total_g; g++) {
        asm volatile("cp.async.wait_group 2;\n" ::: "memory");
        __syncthreads();

        const int l = g + 3;
        if (l < total_g) load_stage(l);
        asm volatile("cp.async.commit_group;\n" ::: "memory");

        const uint32_t stBase = smem_u + (uint32_t)((g & 3) * STAGE) * 2u;
        const uint32_t aTh = stBase + (uint32_t)(aRow * STRIDE + aKc * 8) * 2u;
        const bool half = (g >= FULL_STEPS);

        if (!half) {
            const uint32_t bTh = stBase +
                (uint32_t)(T_ST + bRow * STRIDE + bKc * 8) * 2u;
#pragma unroll
            for (int ks = 0; ks < 2; ks++) {
                const uint32_t ko = (uint32_t)(ks * 16) * 2u;
                uint32_t af[4][4], bf[8][2];
#pragma unroll
                for (int mi = 0; mi < 4; mi++)
                    ldsm4(af[mi][0], af[mi][1], af[mi][2], af[mi][3],
                          aTh + (uint32_t)(mi * 16 * STRIDE) * 2u + ko);
#pragma unroll
                for (int nj = 0; nj < 4; nj++)
                    ldsm4(bf[2 * nj][0], bf[2 * nj][1], bf[2 * nj + 1][0],
                          bf[2 * nj + 1][1],
                          bTh + (uint32_t)(nj * 16 * STRIDE) * 2u + ko);
#pragma unroll
                for (int mi = 0; mi < 4; mi++)
#pragma unroll
                    for (int ni = 0; ni < 8; ni++)
                        mma16(acc[mi][ni], af[mi], bf[ni]);
            }
        } else {
            const uint32_t bTh = stBase +
                (uint32_t)(T_ST + bRowH * STRIDE + bKc * 8) * 2u;
#pragma unroll
            for (int ks = 0; ks < 2; ks++) {
                const uint32_t ko = (uint32_t)(ks * 16) * 2u;
                uint32_t af[4][4], bf[4][2];
#pragma unroll
                for (int mi = 0; mi < 4; mi++)
                    ldsm4(af[mi][0], af[mi][1], af[mi][2], af[mi][3],
                          aTh + (uint32_t)(mi * 16 * STRIDE) * 2u + ko);
                ldsm4(bf[0][0], bf[0][1], bf[1][0], bf[1][1], bTh + ko);
                ldsm4(bf[2][0], bf[2][1], bf[3][0], bf[3][1],
                      bTh + (uint32_t)(16 * STRIDE) * 2u + ko);
#pragma unroll
                for (int mi = 0; mi < 4; mi++)
#pragma unroll
                    for (int ni = 0; ni < 4; ni++)
                        mma16(acc[mi][ni], af[mi], bf[ni]);
            }
        }

        // Tile boundary (both full and half segments are 64 steps long).
        if ((g & (KTILES - 1)) == KTILES - 1) {
            if (!half) {
                const int tl = cta + (g >> 6) * GRID;
                const int bM = (tl >> 6) * 128;
                const int bN = (tl & 63) * 128;
#pragma unroll
                for (int mi = 0; mi < 4; mi++) {
                    const int r0 = bM + wm * 64 + mi * 16 + grp;
#pragma unroll
                    for (int ni = 0; ni < 8; ni++) {
                        const int c0 = bN + wn * 64 + ni * 8 + 2 * tig;
                        float2 v0 = make_float2(acc[mi][ni][0], acc[mi][ni][1]);
                        float2 v1 = make_float2(acc[mi][ni][2], acc[mi][ni][3]);
                        __stcs(reinterpret_cast<float2*>(C + (size_t)r0 * N_DIM + c0), v0);
                        __stcs(reinterpret_cast<float2*>(C + (size_t)(r0 + 8) * N_DIM + c0), v1);
#pragma unroll
                        for (int q = 0; q < 4; q++) acc[mi][ni][q] = 0.f;
                    }
                }
            } else {
#pragma unroll
                for (int mi = 0; mi < 4; mi++) {
                    const int r0 = hbM + wm * 64 + mi * 16 + grp;
#pragma unroll
                    for (int ni = 0; ni < 4; ni++) {
                        const int c0 = hbN + wn * 32 + ni * 8 + 2 * tig;
                        float2 v0 = make_float2(acc[mi][ni][0], acc[mi][ni][1]);
                        float2 v1 = make_float2(acc[mi][ni][2], acc[mi][ni][3]);
                        __stcs(reinterpret_cast<float2*>(C + (size_t)r0 * N_DIM + c0), v0);
                        __stcs(reinterpret_cast<float2*>(C + (size_t)(r0 + 8) * N_DIM + c0), v1);
                    }
                }
            }
        }
    }
}

// ---------------------------------------------------------------------------
extern "C" void kernel_launch(void* const* d_in, const int* in_sizes, int n_in,
                              void* d_out, int out_size) {
    const float* x  = (const float*)d_in[0];  // [8192,2048]
    const float* w  = (const float*)d_in[1];  // [2048,8192]
    const float* la = (const float*)d_in[2];  // [2048,16]
    const float* lb = (const float*)d_in[3];  // [16,8192]
    float* out = (float*)d_out;               // [8192,8192]

    void *xh_p = nullptr, *wh_p = nullptr;
    cudaGetSymbolAddress(&xh_p, g_xh);
    cudaGetSymbolAddress(&wh_p, g_wh);

    prep_x<<<(int)(((size_t)M_DIM * K_DIM / 8) / 256), 256>>>(
        (const float4*)x, (uint4*)xh_p);
    fuse_w_t<<<dim3(N_DIM / 32, K_DIM / 64), 256>>>(w, la, lb);

    cudaFuncSetAttribute(gemm_f16, cudaFuncAttributeMaxDynamicSharedMemorySize, SMEM_BYTES);
    gemm_f16<<<GRID, 128, SMEM_BYTES>>>(
        (const __half*)xh_p, (const __half*)wh_p, out);
}

// round 17
// speedup vs baseline: 1.0122x; 1.0122x over previous
#include <cuda_runtime.h>
#include <cuda_fp16.h>
#include <cstdint>
#include <cstddef>

// out[M,N] = x[M,K] @ (w[K,N] + 2 * lora_a[K,16] @ lora_b[16,N])
#define M_DIM 8192
#define N_DIM 8192
#define K_DIM 2048
#define SCALE 2.0f

// Scratch (device globals — allocation-free per harness rules).
__device__ __align__(16) __half g_xh[(size_t)M_DIM * K_DIM];  // x -> fp16 [M,K]
__device__ __align__(16) __half g_wh[(size_t)N_DIM * K_DIM];  // W'^T fp16 [N,K]

// ---------------------------------------------------------------------------
// Kernel 1: x -> fp16. 4 independent float4 loads per thread (MLP=4),
// streaming stores (output is consumed much later; don't cache 32 MB).
// ---------------------------------------------------------------------------
__global__ __launch_bounds__(256) void prep_x(const float4* __restrict__ x,
                                              uint4* __restrict__ xh) {
    const size_t i = (size_t)blockIdx.x * 256 + threadIdx.x;
    const float4 v0 = x[i * 4 + 0];
    const float4 v1 = x[i * 4 + 1];
    const float4 v2 = x[i * 4 + 2];
    const float4 v3 = x[i * 4 + 3];
    __half2 h0[4], h1[4];
    h0[0] = __floats2half2_rn(v0.x, v0.y);
    h0[1] = __floats2half2_rn(v0.z, v0.w);
    h0[2] = __floats2half2_rn(v1.x, v1.y);
    h0[3] = __floats2half2_rn(v1.z, v1.w);
    h1[0] = __floats2half2_rn(v2.x, v2.y);
    h1[1] = __floats2half2_rn(v2.z, v2.w);
    h1[2] = __floats2half2_rn(v3.x, v3.y);
    h1[3] = __floats2half2_rn(v3.z, v3.w);
    __stcs(&xh[i * 2 + 0], *reinterpret_cast<const uint4*>(h0));
    __stcs(&xh[i * 2 + 1], *reinterpret_cast<const uint4*>(h1));
}

// ---------------------------------------------------------------------------
// Kernel 2: g_wh[n][k] = fp16(w[k][n] + 2*(A@B)[k][n]).
// Tile 64k x 32n per block; uint4-packed coalesced streaming stores.
// ---------------------------------------------------------------------------
__global__ __launch_bounds__(256) void fuse_w_t(const float* __restrict__ w,
                                                const float* __restrict__ la,
                                                const float* __restrict__ lb) {
    __shared__ float t[64][33];
    __shared__ float bs[16][32];
    const int n0 = blockIdx.x * 32, k0 = blockIdx.y * 64;
    const int tid = threadIdx.x;
    const int tx = tid & 31, ty = tid >> 5;
    {
        int i0 = tid;
        bs[i0 >> 5][i0 & 31] = lb[(size_t)(i0 >> 5) * N_DIM + n0 + (i0 & 31)];
        int i1 = tid + 256;
        bs[i1 >> 5][i1 & 31] = lb[(size_t)(i1 >> 5) * N_DIM + n0 + (i1 & 31)];
    }
    __syncthreads();
#pragma unroll
    for (int i = 0; i < 8; i++) {
        const int kl = ty + 8 * i;           // 0..63
        const int k = k0 + kl;
        const float* ar = la + (size_t)k * 16;
        float acc = 0.f;
#pragma unroll
        for (int r = 0; r < 16; r++) acc += ar[r] * bs[r][tx];
        t[kl][tx] = w[(size_t)k * N_DIM + n0 + tx] + SCALE * acc;
    }
    __syncthreads();
    const int nl = tid >> 3;                 // 0..31
    const int kc = (tid & 7) * 8;            // 0..56
    __half2 h[4];
#pragma unroll
    for (int j = 0; j < 4; j++)
        h[j] = __halves2half2(__float2half_rn(t[kc + 2 * j][nl]),
                              __float2half_rn(t[kc + 2 * j + 1][nl]));
    __stcs(reinterpret_cast<uint4*>(&g_wh[(size_t)(n0 + nl) * K_DIM + k0 + kc]),
           *reinterpret_cast<const uint4*>(h));
}

// ---------------------------------------------------------------------------
// Kernel 3: PERSISTENT fp16 mma.sync GEMM (f32 accum). 304 CTAs (2/SM),
// 128 threads, 4 warps of 64x64 (2 warps/SMSP). KTILE=32, 4 stages,
// wait_group 2 -> barrier never waits on memory. ldmatrix fragments.
// (Exact round-12/15 configuration — best measured.)
// ---------------------------------------------------------------------------
constexpr int KTILE = 32;                   // halves per k-tile
constexpr int STRIDE = 40;                  // 80 B rows; LDSM banks 20r distinct
constexpr int T_ST = 128 * STRIDE;          // 5120 halves (10 KB)
constexpr int STAGE = 2 * T_ST;             // A + B per stage (20 KB)
constexpr int SMEM_BYTES = 4 * STAGE * 2;   // 81920 B (x2 CTAs = 160 KB)
constexpr int KTILES = K_DIM / KTILE;       // 64 steps per tile
constexpr int NT = (M_DIM / 128) * (N_DIM / 128);  // 4096 tiles
constexpr int GRID = 304;                   // 152 SMs x 2 CTAs

__device__ __forceinline__ void ldsm4(uint32_t& r0, uint32_t& r1, uint32_t& r2,
                                      uint32_t& r3, uint32_t addr) {
    asm volatile("ldmatrix.sync.aligned.m8n8.x4.shared.b16 {%0,%1,%2,%3}, [%4];"
                 : "=r"(r0), "=r"(r1), "=r"(r2), "=r"(r3) : "r"(addr));
}
__device__ __forceinline__ void mma16(float c[4], const uint32_t a[4], const uint32_t b[2]) {
    asm volatile(
        "mma.sync.aligned.m16n8k16.row.col.f32.f16.f16.f32 "
        "{%0,%1,%2,%3}, {%4,%5,%6,%7}, {%8,%9}, {%0,%1,%2,%3};\n"
        : "+f"(c[0]), "+f"(c[1]), "+f"(c[2]), "+f"(c[3])
        : "r"(a[0]), "r"(a[1]), "r"(a[2]), "r"(a[3]), "r"(b[0]), "r"(b[1]));
}

__global__ __launch_bounds__(128, 2) void gemm_f16(const __half* __restrict__ A,
                                                   const __half* __restrict__ B,
                                                   float* __restrict__ C) {
    extern __shared__ __half smem[];
    const int tid = threadIdx.x;
    const int lane = tid & 31;
    const int warp = tid >> 5;   // 0..3
    const int wm = warp >> 1;    // 2 warps along M (64 rows)
    const int wn = warp & 1;     // 2 warps along N (64 cols)
    const int grp = lane >> 2;   // 0..7
    const int tig = lane & 3;    // 0..3
    const int cta = blockIdx.x;

    const uint32_t smem_u = (uint32_t)__cvta_generic_to_shared(smem);

    const int nt = (NT - cta + GRID - 1) / GRID;   // tiles for this CTA (13/14)
    const int total_g = nt * KTILES;

    float acc[4][8][4];
#pragma unroll
    for (int i = 0; i < 4; i++)
#pragma unroll
        for (int j = 0; j < 8; j++)
#pragma unroll
            for (int l = 0; l < 4; l++) acc[i][j][l] = 0.f;

    // Pipeline step l: tile ordinal l/64, k-chunk l%64, stage l&3.
    auto load_stage = [&](int l) {
        const int tl = cta + (l >> 6) * GRID;      // global tile index
        const int bM = (tl >> 6) * 128;
        const int bN = (tl & 63) * 128;
        const int k0 = (l & 63) * KTILE;
        const uint32_t baseA = smem_u + (uint32_t)((l & 3) * STAGE) * 2u;
        const uint32_t baseB = baseA + (uint32_t)T_ST * 2u;
#pragma unroll
        for (int i = 0; i < 4; i++) {
            const int idx = tid + i * 128;
            const int row = idx >> 2, ch = idx & 3;
            const __half* g = A + (size_t)(bM + row) * K_DIM + k0 + ch * 8;
            const uint32_t d = baseA + (uint32_t)(row * STRIDE + ch * 8) * 2u;
            asm volatile("cp.async.cg.shared.global [%0], [%1], 16;\n" ::"r"(d), "l"(g));
        }
#pragma unroll
        for (int i = 0; i < 4; i++) {
            const int idx = tid + i * 128;
            const int row = idx >> 2, ch = idx & 3;
            const __half* g = B + (size_t)(bN + row) * K_DIM + k0 + ch * 8;
            const uint32_t d = baseB + (uint32_t)(row * STRIDE + ch * 8) * 2u;
            asm volatile("cp.async.cg.shared.global [%0], [%1], 16;\n" ::"r"(d), "l"(g));
        }
    };

    // Prologue: steps 0,1,2 -> stages 0,1,2
#pragma unroll
    for (int p = 0; p < 3; p++) {
        load_stage(p);
        asm volatile("cp.async.commit_group;\n" ::: "memory");
    }

    // ldmatrix per-thread addresses (mapping validated round 8):
    const int aRow = wm * 64 + (lane & 7) + 8 * ((lane >> 3) & 1);
    const int aKc = (lane >> 4) & 1;
    const int bRow = wn * 64 + (lane & 7) + 8 * ((lane >> 4) & 1);
    const int bKc = (lane >> 3) & 1;

    for (int g = 0; g < total_g; g++) {
        // step g's group complete (committed 3 steps ago); 2 newer in flight
        asm volatile("cp.async.wait_group 2;\n" ::: "memory");
        __syncthreads();

        const int l = g + 3;     // prefetch into stage consumed at step g-1
        if (l < total_g) load_stage(l);
        asm volatile("cp.async.commit_group;\n" ::: "memory");  // 1 group / step

        const uint32_t stBase = smem_u + (uint32_t)((g & 3) * STAGE) * 2u;
        const uint32_t aTh = stBase + (uint32_t)(aRow * STRIDE + aKc * 8) * 2u;
        const uint32_t bTh = stBase + (uint32_t)(T_ST + bRow * STRIDE + bKc * 8) * 2u;
#pragma unroll
        for (int ks = 0; ks < 2; ks++) {          // 2 x k16 per KTILE=32
            const uint32_t ko = (uint32_t)(ks * 16) * 2u;
            uint32_t af[4][4], bf[8][2];
#pragma unroll
            for (int mi = 0; mi < 4; mi++)
                ldsm4(af[mi][0], af[mi][1], af[mi][2], af[mi][3],
                      aTh + (uint32_t)(mi * 16 * STRIDE) * 2u + ko);
#pragma unroll
            for (int nj = 0; nj < 4; nj++)
                ldsm4(bf[2 * nj][0], bf[2 * nj][1], bf[2 * nj + 1][0], bf[2 * nj + 1][1],
                      bTh + (uint32_t)(nj * 16 * STRIDE) * 2u + ko);
#pragma unroll
            for (int mi = 0; mi < 4; mi++)
#pragma unroll
                for (int ni = 0; ni < 8; ni++)
                    mma16(acc[mi][ni], af[mi], bf[ni]);
        }

        // Tile boundary: drain accumulators with streaming stores.
        if ((g & (KTILES - 1)) == KTILES - 1) {
            const int tl = cta + (g >> 6) * GRID;
            const int bM = (tl >> 6) * 128;
            const int bN = (tl & 63) * 128;
#pragma unroll
            for (int mi = 0; mi < 4; mi++) {
                const int r0 = bM + wm * 64 + mi * 16 + grp;
#pragma unroll
                for (int ni = 0; ni < 8; ni++) {
                    const int c0 = bN + wn * 64 + ni * 8 + 2 * tig;
                    float2 v0 = make_float2(acc[mi][ni][0], acc[mi][ni][1]);
                    float2 v1 = make_float2(acc[mi][ni][2], acc[mi][ni][3]);
                    __stcs(reinterpret_cast<float2*>(C + (size_t)r0 * N_DIM + c0), v0);
                    __stcs(reinterpret_cast<float2*>(C + (size_t)(r0 + 8) * N_DIM + c0), v1);
#pragma unroll
                    for (int q = 0; q < 4; q++) acc[mi][ni][q] = 0.f;
                }
            }
        }
    }
}

// ---------------------------------------------------------------------------
extern "C" void kernel_launch(void* const* d_in, const int* in_sizes, int n_in,
                              void* d_out, int out_size) {
    const float* x  = (const float*)d_in[0];  // [8192,2048]
    const float* w  = (const float*)d_in[1];  // [2048,8192]
    const float* la = (const float*)d_in[2];  // [2048,16]
    const float* lb = (const float*)d_in[3];  // [16,8192]
    float* out = (float*)d_out;               // [8192,8192]

    void *xh_p = nullptr, *wh_p = nullptr;
    cudaGetSymbolAddress(&xh_p, g_xh);
    cudaGetSymbolAddress(&wh_p, g_wh);

    prep_x<<<(int)(((size_t)M_DIM * K_DIM / 16) / 256), 256>>>(
        (const float4*)x, (uint4*)xh_p);
    fuse_w_t<<<dim3(N_DIM / 32, K_DIM / 64), 256>>>(w, la, lb);

    cudaFuncSetAttribute(gemm_f16, cudaFuncAttributeMaxDynamicSharedMemorySize, SMEM_BYTES);
    gemm_f16<<<GRID, 128, SMEM_BYTES>>>(
        (const __half*)xh_p, (const __half*)wh_p, out);
}